// round 9
// baseline (speedup 1.0000x reference)
#include <cuda_runtime.h>

// Problem shape
#define B    4
#define T    8192
#define D    512
#define CH   4                 // time steps per chunk (per block)
#define NC   (T / CH)          // 2048 chunks per sequence
#define TPB  128               // threads per block; each owns 4 channels
#define LBW  4                 // lookback window

// Flag states
#define FLG_NONE 0
#define FLG_AGG  1
#define FLG_PREF 2

// Scratch (device globals; zero-initialized at module load).
__device__ float2 g_aggv [B * NC * D];        // per-chunk (a, h_local_end)
__device__ float  g_prefh[B * NC * D];        // per-chunk inclusive-prefix h
__device__ int    g_flag [B * NC * TPB];      // per-(b, chunk, thread)

__device__ __forceinline__ float tanha(float x) {
    float y;
    asm("tanh.approx.f32 %0, %1;" : "=f"(y) : "f"(x));
    return y;
}
__device__ __forceinline__ float sigm(float x) {
    return fmaf(tanha(0.5f * x), 0.5f, 0.5f);
}
__device__ __forceinline__ void st_release(int* p, int v) {
    asm volatile("st.release.gpu.global.b32 [%0], %1;" :: "l"(p), "r"(v) : "memory");
}
__device__ __forceinline__ int ld_acquire(const int* p) {
    int v;
    asm volatile("ld.acquire.gpu.global.b32 %0, [%1];" : "=r"(v) : "l"(p) : "memory");
    return v;
}

__global__ void __launch_bounds__(TPB, 8)
scan_onepass(const float* __restrict__ x, float* __restrict__ out) {
    // Per-thread-private stashes (no cross-thread sharing, no __syncthreads).
    __shared__ float4 sm_f [CH * TPB];   // forget gates (4 ch)
    __shared__ float4 sm_iv[CH * TPB];   // i * tanh(v)   (4 ch)
    __shared__ float4 sm_go[CH * TPB];   // raw output-gate inputs (4 ch)

    const int c   = blockIdx.x;          // chunk (predecessors have lower bid)
    const int b   = blockIdx.y;          // batch
    const int tid = threadIdx.x;
    const int d   = tid * 4;             // channel base (owns 4)

    const float* base  = x   + ((size_t)b * T + (size_t)c * CH) * (3 * D) + d;
    float*       obase = out + ((size_t)b * T + (size_t)c * CH) * D + d;

    // ------- Phase 1a: batch ALL vi/gi loads first (max MLP, LDG.128) ------
    float4 V[CH], G[CH];
#pragma unroll
    for (int t = 0; t < CH; ++t) {
        V[t] = __ldcs((const float4*)(base + (size_t)t * (3 * D)));
        G[t] = __ldcs((const float4*)(base + (size_t)t * (3 * D) + D));
    }

    // ------- Phase 1b: local chunk scan, stash f and i*v into smem ---------
    float a0 = 1.f, a1 = 1.f, a2 = 1.f, a3 = 1.f;
    float h0 = 0.f, h1 = 0.f, h2 = 0.f, h3 = 0.f;
#pragma unroll
    for (int t = 0; t < CH; ++t) {
        float i0 = sigm(G[t].x), i1 = sigm(G[t].y), i2 = sigm(G[t].z), i3 = sigm(G[t].w);
        float f0 = 1.f - i0,     f1 = 1.f - i1,     f2 = 1.f - i2,     f3 = 1.f - i3;
        float w0 = i0 * tanha(V[t].x), w1 = i1 * tanha(V[t].y);
        float w2 = i2 * tanha(V[t].z), w3 = i3 * tanha(V[t].w);

        sm_f [t * TPB + tid] = make_float4(f0, f1, f2, f3);
        sm_iv[t * TPB + tid] = make_float4(w0, w1, w2, w3);

        a0 *= f0; a1 *= f1; a2 *= f2; a3 *= f3;
        h0 = fmaf(f0, h0, w0);
        h1 = fmaf(f1, h1, w1);
        h2 = fmaf(f2, h2, w2);
        h3 = fmaf(f3, h3, w3);
    }

    // Pull the output-gate stream now (overlaps lookback), park it in smem
    // so it doesn't hold registers across the lookback.
#pragma unroll
    for (int t = 0; t < CH; ++t)
        sm_go[t * TPB + tid] = __ldcs((const float4*)(base + (size_t)t * (3 * D) + 2 * D));

    const size_t sidx  = ((size_t)b * NC + c) * D + d;   // value index (4 ch)
    const int    fbase = (b * NC) * TPB + tid;           // flag index helper

    float He0 = 0.f, He1 = 0.f, He2 = 0.f, He3 = 0.f;   // exclusive prefix h

    if (c == 0) {
        __stcg((float4*)&g_prefh[sidx], make_float4(h0, h1, h2, h3));
        st_release(&g_flag[fbase + 0 * TPB], FLG_PREF);
    } else {
        __stcg((float4*)&g_aggv[sidx + 0], make_float4(a0, h0, a1, h1));
        __stcg((float4*)&g_aggv[sidx + 2], make_float4(a2, h2, a3, h3));
        st_release(&g_flag[fbase + c * TPB], FLG_AGG);

        // ------- Phase 2: decoupled lookback --------------------------------
        float As0 = 1.f, As1 = 1.f, As2 = 1.f, As3 = 1.f;
        float Bs0 = 0.f, Bs1 = 0.f, Bs2 = 0.f, Bs3 = 0.f;

        int p = c - 1;
        bool done = false;
        while (!done) {
            const int w = (p + 1 < LBW) ? (p + 1) : LBW;

            int fl[LBW];
            for (;;) {
                bool all = true;
#pragma unroll
                for (int k = 0; k < LBW; ++k) {
                    if (k < w) {
                        fl[k] = ld_acquire(&g_flag[fbase + (p - k) * TPB]);
                        all &= (fl[k] != FLG_NONE);
                    }
                }
                if (all) break;
            }

            int kpref = -1;
#pragma unroll
            for (int k = 0; k < LBW; ++k)
                if (k < w && kpref < 0 && fl[k] == FLG_PREF) kpref = k;
            const int kend = (kpref >= 0) ? kpref : (w - 1);

            for (int k = 0; k <= kend; ++k) {
                const size_t vb = ((size_t)b * NC + (p - k)) * D + d;
                if (k == kpref) {
                    float4 pv = __ldcg((const float4*)&g_prefh[vb]);
                    He0 = fmaf(As0, pv.x, Bs0);
                    He1 = fmaf(As1, pv.y, Bs1);
                    He2 = fmaf(As2, pv.z, Bs2);
                    He3 = fmaf(As3, pv.w, Bs3);
                    done = true;
                    break;
                } else {
                    float4 qa = __ldcg((const float4*)&g_aggv[vb + 0]);
                    float4 qb = __ldcg((const float4*)&g_aggv[vb + 2]);
                    Bs0 = fmaf(As0, qa.y, Bs0); As0 *= qa.x;
                    Bs1 = fmaf(As1, qa.w, Bs1); As1 *= qa.z;
                    Bs2 = fmaf(As2, qb.y, Bs2); As2 *= qb.x;
                    Bs3 = fmaf(As3, qb.w, Bs3); As3 *= qb.z;
                }
            }
            if (!done) {
                p -= w;
                if (p < 0) {
                    He0 = Bs0; He1 = Bs1; He2 = Bs2; He3 = Bs3;
                    done = true;
                }
            }
        }

        __stcg((float4*)&g_prefh[sidx],
               make_float4(fmaf(a0, He0, h0), fmaf(a1, He1, h1),
                           fmaf(a2, He2, h2), fmaf(a3, He3, h3)));
        st_release(&g_flag[fbase + c * TPB], FLG_PREF);
    }

    // ------- Phase 3: replay from smem stash, emit --------------------------
    float k0 = He0, k1 = He1, k2 = He2, k3 = He3;
#pragma unroll
    for (int t = 0; t < CH; ++t) {
        const float4 ff = sm_f [t * TPB + tid];
        const float4 iv = sm_iv[t * TPB + tid];
        const float4 go = sm_go[t * TPB + tid];

        k0 = fmaf(ff.x, k0, iv.x);
        k1 = fmaf(ff.y, k1, iv.y);
        k2 = fmaf(ff.z, k2, iv.z);
        k3 = fmaf(ff.w, k3, iv.w);

        float4 o4;
        o4.x = tanha(k0) * sigm(go.x);
        o4.y = tanha(k1) * sigm(go.y);
        o4.z = tanha(k2) * sigm(go.z);
        o4.w = tanha(k3) * sigm(go.w);
        __stcs((float4*)(obase + (size_t)t * D), o4);
    }
}

extern "C" void kernel_launch(void* const* d_in, const int* in_sizes, int n_in,
                              void* d_out, int out_size) {
    const float* x = (const float*)d_in[0];
    float* out = (float*)d_out;

    dim3 grid(NC, B);   // 2048 x 4 = 8192 blocks; blockIdx.x = chunk (bid-ordered)
    scan_onepass<<<grid, TPB>>>(x, out);
}